// round 13
// baseline (speedup 1.0000x reference)
#include <cuda_runtime.h>
#include <math.h>

#define NN      50000
#define EE      800000
#define ET      (EE + NN)      // edges + self loops
#define F_IN    128
#define HID     64
#define HEADS   4
#define D1      (HID * HEADS)  // 256
#define OUT_F   64
#define NGRAPH  512
#define NEG_SLOPE 0.2f

// ---------------- scratch (static device globals; no runtime alloc) ----------------
__device__ float g_bufA[NN * D1];    // 51.2 MB   (GEMM output h)
__device__ float g_bufB[NN * D1];    // 51.2 MB   (layer output after agg+ELU)
__device__ float g_as[NN * HEADS];
__device__ float g_ad[NN * HEADS];
__device__ int   g_deg[NN];
__device__ int   g_fill[NN];
__device__ int   g_tmp[NN];
__device__ int   g_rowptr[NN + 1];
__device__ int   g_csr[ET];
__device__ int   g_blocksum[64];
__device__ int   g_blockoff[64];
__device__ float g_pooled[NGRAPH * D1];

// ---------------- CSR build ----------------
__global__ void k_zero() {
    for (int i = blockIdx.x * blockDim.x + threadIdx.x; i < NN; i += gridDim.x * blockDim.x) {
        g_deg[i] = 0;
        g_fill[i] = 0;
    }
}

__global__ void k_hist(const int* __restrict__ ei) {
    int i = blockIdx.x * blockDim.x + threadIdx.x;
    if (i >= ET) return;
    int d = (i < EE) ? ei[EE + i] : (i - EE);
    atomicAdd(&g_deg[d], 1);
}

// block-level inclusive scan, chunk = 4096 per block (1024 thr x 4 elems)
__global__ void k_scan_part() {
    __shared__ int sh[1024];
    int tid = threadIdx.x;
    int idx0 = blockIdx.x * 4096 + tid * 4;
    int v[4];
    int s = 0;
#pragma unroll
    for (int j = 0; j < 4; j++) {
        v[j] = (idx0 + j < NN) ? g_deg[idx0 + j] : 0;
        s += v[j];
    }
    sh[tid] = s;
    __syncthreads();
    for (int off = 1; off < 1024; off <<= 1) {
        int t = (tid >= off) ? sh[tid - off] : 0;
        __syncthreads();
        sh[tid] += t;
        __syncthreads();
    }
    int run = sh[tid] - s;  // exclusive prefix of this thread
#pragma unroll
    for (int j = 0; j < 4; j++) {
        run += v[j];
        if (idx0 + j < NN) g_tmp[idx0 + j] = run;  // inclusive within block
    }
    if (tid == 1023) g_blocksum[blockIdx.x] = sh[1023];
}

__global__ void k_scan_sums(int nb) {
    if (threadIdx.x == 0 && blockIdx.x == 0) {
        int run = 0;
        for (int b = 0; b < nb; b++) {
            int t = g_blocksum[b];
            g_blockoff[b] = run;
            run += t;
        }
    }
}

__global__ void k_scan_add() {
    int i = blockIdx.x * blockDim.x + threadIdx.x;
    if (i >= NN) return;
    g_rowptr[i + 1] = g_tmp[i] + g_blockoff[i >> 12];
    if (i == 0) g_rowptr[0] = 0;
}

__global__ void k_fill_csr(const int* __restrict__ ei) {
    int i = blockIdx.x * blockDim.x + threadIdx.x;
    if (i >= ET) return;
    int s, d;
    if (i < EE) { s = ei[i]; d = ei[EE + i]; }
    else        { s = d = i - EE; }
    int pos = g_rowptr[d] + atomicAdd(&g_fill[d], 1);
    g_csr[pos] = s;
}

// ---------------- GEMM: g_bufA[M,Ncol] = A[M,K] @ B[K,Ncol] ----------------
// A = Aext if useExt, else g_bufB. 64x64 tile, BK=8, 256 threads, 4x4 microtile.
__global__ void k_gemm(const float* __restrict__ Aext, const float* __restrict__ B,
                       int useExt, int M, int K, int Ncol) {
    const float* __restrict__ A = useExt ? Aext : (const float*)g_bufB;
    float* __restrict__ C = g_bufA;
    __shared__ float As[8][64];
    __shared__ float Bs[8][64];
    int tid = threadIdx.x;
    int tx = tid & 15, ty = tid >> 4;
    int rowBase = blockIdx.y * 64;
    int colBase = blockIdx.x * 64;
    float acc[4][4] = {};
    int a_m = tid >> 2;
    int a_k = (tid & 3) * 2;
    int b_k = tid >> 5;
    int b_n = (tid & 31) * 2;

    for (int k0 = 0; k0 < K; k0 += 8) {
        float2 av = make_float2(0.f, 0.f);
        int arow = rowBase + a_m;
        if (arow < M) av = *(const float2*)(A + (size_t)arow * K + k0 + a_k);
        As[a_k][a_m] = av.x;
        As[a_k + 1][a_m] = av.y;
        float2 bv = *(const float2*)(B + (size_t)(k0 + b_k) * Ncol + colBase + b_n);
        Bs[b_k][b_n] = bv.x;
        Bs[b_k][b_n + 1] = bv.y;
        __syncthreads();
#pragma unroll
        for (int kk = 0; kk < 8; kk++) {
            float a[4], b[4];
#pragma unroll
            for (int i = 0; i < 4; i++) a[i] = As[kk][ty * 4 + i];
#pragma unroll
            for (int j = 0; j < 4; j++) b[j] = Bs[kk][tx * 4 + j];
#pragma unroll
            for (int i = 0; i < 4; i++)
#pragma unroll
                for (int j = 0; j < 4; j++) acc[i][j] += a[i] * b[j];
        }
        __syncthreads();
    }
#pragma unroll
    for (int i = 0; i < 4; i++) {
        int row = rowBase + ty * 4 + i;
        if (row < M) {
            float4 v = make_float4(acc[i][0], acc[i][1], acc[i][2], acc[i][3]);
            *(float4*)(C + (size_t)row * Ncol + colBase + tx * 4) = v;
        }
    }
}

// ---------------- attention logits: warp per (node, head), reads g_bufA ----------------
__global__ void k_logits(const float* __restrict__ att_src,
                         const float* __restrict__ att_dst) {
    int wid = (blockIdx.x * blockDim.x + threadIdx.x) >> 5;
    int lane = threadIdx.x & 31;
    if (wid >= NN * HEADS) return;
    int n = wid >> 2, head = wid & 3;
    float2 hv = *(const float2*)(g_bufA + (size_t)n * D1 + head * HID + lane * 2);
    float2 as = *(const float2*)(att_src + head * HID + lane * 2);
    float2 ad = *(const float2*)(att_dst + head * HID + lane * 2);
    float ds = hv.x * as.x + hv.y * as.y;
    float dd = hv.x * ad.x + hv.y * ad.y;
#pragma unroll
    for (int off = 16; off > 0; off >>= 1) {
        ds += __shfl_xor_sync(0xffffffffu, ds, off);
        dd += __shfl_xor_sync(0xffffffffu, dd, off);
    }
    if (lane == 0) {
        g_as[n * HEADS + head] = ds;
        g_ad[n * HEADS + head] = dd;
    }
}

// ---------------- aggregation: warp per (node, head), online softmax ----------------
// reads g_bufA (h) + g_as/g_ad + CSR, writes g_bufB (with bias + ELU)
__global__ void k_agg(const float* __restrict__ bias) {
    int wid = (blockIdx.x * blockDim.x + threadIdx.x) >> 5;
    int lane = threadIdx.x & 31;
    if (wid >= NN * HEADS) return;
    int n = wid >> 2, head = wid & 3;
    int beg = g_rowptr[n], end = g_rowptr[n + 1];
    float adv = g_ad[n * HEADS + head];
    const float* hh = (const float*)g_bufA + head * HID + lane * 2;

    float m = -1e30f, s = 0.f, ax = 0.f, ay = 0.f;
    for (int p = beg; p < end; p++) {
        int sn = g_csr[p];
        float e = g_as[sn * HEADS + head] + adv;
        e = (e > 0.f) ? e : NEG_SLOPE * e;
        float mn = fmaxf(m, e);
        float c = __expf(m - mn);
        float w = __expf(e - mn);
        float2 hv = *(const float2*)(hh + (size_t)sn * D1);
        s = s * c + w;
        ax = ax * c + w * hv.x;
        ay = ay * c + w * hv.y;
        m = mn;
    }
    float inv = 1.f / s;
    int o = n * D1 + head * HID + lane * 2;
    float o0 = ax * inv + bias[head * HID + lane * 2];
    float o1 = ay * inv + bias[head * HID + lane * 2 + 1];
    // ELU
    o0 = (o0 > 0.f) ? o0 : expm1f(o0);
    o1 = (o1 > 0.f) ? o1 : expm1f(o1);
    *(float2*)(g_bufB + o) = make_float2(o0, o1);
}

// ---------------- global mean pool (batch sorted int32), reads g_bufB ----------------
__device__ int lower_bound_i(const int* a, int n, int v) {
    int lo = 0, hi = n;
    while (lo < hi) {
        int mid = (lo + hi) >> 1;
        if (a[mid] < v) lo = mid + 1; else hi = mid;
    }
    return lo;
}

__global__ void k_pool(const int* __restrict__ batch) {
    __shared__ int s_lo, s_hi;
    int g = blockIdx.x;
    int tid = threadIdx.x;
    if (tid == 0) {
        s_lo = lower_bound_i(batch, NN, g);
        s_hi = lower_bound_i(batch, NN, g + 1);
    }
    __syncthreads();
    int lo = s_lo, hi = s_hi;
    float acc = 0.f;
    for (int n = lo; n < hi; n++) acc += g_bufB[(size_t)n * D1 + tid];
    float cnt = (float)(hi - lo);
    g_pooled[g * D1 + tid] = acc / fmaxf(cnt, 1.f);
}

// ---------------- final linear ----------------
__global__ void k_fc(const float* __restrict__ fc_w, const float* __restrict__ fc_b,
                     float* __restrict__ out) {
    __shared__ float sp[D1];
    int g = blockIdx.x;
    int tid = threadIdx.x;  // 64 threads
    for (int i = tid; i < D1; i += 64) sp[i] = g_pooled[g * D1 + i];
    __syncthreads();
    float acc = fc_b[tid];
#pragma unroll 8
    for (int k = 0; k < D1; k++) acc += sp[k] * fc_w[k * OUT_F + tid];
    out[g * OUT_F + tid] = acc;
}

// ---------------- launch (pure kernel launches; no runtime APIs) ----------------
extern "C" void kernel_launch(void* const* d_in, const int* in_sizes, int n_in,
                              void* d_out, int out_size) {
    const float* x        = (const float*)d_in[0];
    const int*   ei       = (const int*)d_in[1];     // int64 in reference -> int32 in harness
    const int*   bat      = (const int*)d_in[2];     // int64 in reference -> int32 in harness
    const float* W1       = (const float*)d_in[3];
    const float* att_src1 = (const float*)d_in[4];
    const float* att_dst1 = (const float*)d_in[5];
    const float* b1       = (const float*)d_in[6];
    const float* W2       = (const float*)d_in[7];
    const float* att_src2 = (const float*)d_in[8];
    const float* att_dst2 = (const float*)d_in[9];
    const float* b2       = (const float*)d_in[10];
    const float* fc_w     = (const float*)d_in[11];
    const float* fc_b     = (const float*)d_in[12];
    float* out = (float*)d_out;

    const int ZB = 256;
    // CSR build
    k_zero<<<196, ZB>>>();
    k_hist<<<(ET + ZB - 1) / ZB, ZB>>>(ei);
    int nb = (NN + 4095) / 4096;  // 13
    k_scan_part<<<nb, 1024>>>();
    k_scan_sums<<<1, 32>>>(nb);
    k_scan_add<<<(NN + ZB - 1) / ZB, ZB>>>();
    k_fill_csr<<<(ET + ZB - 1) / ZB, ZB>>>(ei);

    dim3 ggrid(D1 / 64, (NN + 63) / 64);
    int warpBlocks = (NN * HEADS * 32 + 255) / 256;  // 25000

    // layer 1: x -> g_bufA -> (logits) -> agg+ELU -> g_bufB
    k_gemm<<<ggrid, 256>>>(x, W1, 1, NN, F_IN, D1);
    k_logits<<<warpBlocks, 256>>>(att_src1, att_dst1);
    k_agg<<<warpBlocks, 256>>>(b1);

    // layer 2: g_bufB -> g_bufA -> (logits) -> agg+ELU -> g_bufB
    k_gemm<<<ggrid, 256>>>(nullptr, W2, 0, NN, D1, D1);
    k_logits<<<warpBlocks, 256>>>(att_src2, att_dst2);
    k_agg<<<warpBlocks, 256>>>(b2);

    // pool + fc
    k_pool<<<NGRAPH, D1>>>(bat);
    k_fc<<<NGRAPH, OUT_F>>>(fc_w, fc_b, out);
}

// round 14
// speedup vs baseline: 1.2204x; 1.2204x over previous
#include <cuda_runtime.h>
#include <math.h>

#define NN      50000
#define EE      800000
#define ET      (EE + NN)      // edges + self loops
#define F_IN    128
#define HID     64
#define HEADS   4
#define D1      (HID * HEADS)  // 256
#define OUT_F   64
#define NGRAPH  512
#define NEG_SLOPE 0.2f

// ---------------- scratch (static device globals; no runtime alloc) ----------------
__device__ float g_bufA[NN * D1];    // 51.2 MB   (GEMM output h)
__device__ float g_bufB[NN * D1];    // 51.2 MB   (layer output after agg+ELU)
__device__ float g_as[NN * HEADS];
__device__ float g_ad[NN * HEADS];
__device__ int   g_deg[NN];
__device__ int   g_fill[NN];
__device__ int   g_tmp[NN];
__device__ int   g_rowptr[NN + 1];
__device__ int   g_csr[ET];
__device__ int   g_blocksum[64];
__device__ int   g_blockoff[64];
__device__ float g_pooled[NGRAPH * D1];

// ---------------- CSR build ----------------
__global__ void k_zero() {
    for (int i = blockIdx.x * blockDim.x + threadIdx.x; i < NN; i += gridDim.x * blockDim.x) {
        g_deg[i] = 0;
        g_fill[i] = 0;
    }
}

__global__ void k_hist(const int* __restrict__ ei) {
    int i = blockIdx.x * blockDim.x + threadIdx.x;
    if (i >= ET) return;
    int d = (i < EE) ? ei[EE + i] : (i - EE);
    atomicAdd(&g_deg[d], 1);
}

// block-level inclusive scan, chunk = 4096 per block (1024 thr x 4 elems)
__global__ void k_scan_part() {
    __shared__ int sh[1024];
    int tid = threadIdx.x;
    int idx0 = blockIdx.x * 4096 + tid * 4;
    int v[4];
    int s = 0;
#pragma unroll
    for (int j = 0; j < 4; j++) {
        v[j] = (idx0 + j < NN) ? g_deg[idx0 + j] : 0;
        s += v[j];
    }
    sh[tid] = s;
    __syncthreads();
    for (int off = 1; off < 1024; off <<= 1) {
        int t = (tid >= off) ? sh[tid - off] : 0;
        __syncthreads();
        sh[tid] += t;
        __syncthreads();
    }
    int run = sh[tid] - s;  // exclusive prefix of this thread
#pragma unroll
    for (int j = 0; j < 4; j++) {
        run += v[j];
        if (idx0 + j < NN) g_tmp[idx0 + j] = run;  // inclusive within block
    }
    if (tid == 1023) g_blocksum[blockIdx.x] = sh[1023];
}

__global__ void k_scan_sums(int nb) {
    if (threadIdx.x == 0 && blockIdx.x == 0) {
        int run = 0;
        for (int b = 0; b < nb; b++) {
            int t = g_blocksum[b];
            g_blockoff[b] = run;
            run += t;
        }
    }
}

__global__ void k_scan_add() {
    int i = blockIdx.x * blockDim.x + threadIdx.x;
    if (i >= NN) return;
    g_rowptr[i + 1] = g_tmp[i] + g_blockoff[i >> 12];
    if (i == 0) g_rowptr[0] = 0;
}

__global__ void k_fill_csr(const int* __restrict__ ei) {
    int i = blockIdx.x * blockDim.x + threadIdx.x;
    if (i >= ET) return;
    int s, d;
    if (i < EE) { s = ei[i]; d = ei[EE + i]; }
    else        { s = d = i - EE; }
    int pos = g_rowptr[d] + atomicAdd(&g_fill[d], 1);
    g_csr[pos] = s;
}

// ---------------- GEMM: g_bufA[M,Ncol] = A[M,K] @ B[K,Ncol] ----------------
// A = Aext if useExt, else g_bufB. 64x64 tile, BK=8, 256 threads, 4x4 microtile.
__global__ void k_gemm(const float* __restrict__ Aext, const float* __restrict__ B,
                       int useExt, int M, int K, int Ncol) {
    const float* __restrict__ A = useExt ? Aext : (const float*)g_bufB;
    float* __restrict__ C = g_bufA;
    __shared__ float As[8][64];
    __shared__ float Bs[8][64];
    int tid = threadIdx.x;
    int tx = tid & 15, ty = tid >> 4;
    int rowBase = blockIdx.y * 64;
    int colBase = blockIdx.x * 64;
    float acc[4][4] = {};
    int a_m = tid >> 2;
    int a_k = (tid & 3) * 2;
    int b_k = tid >> 5;
    int b_n = (tid & 31) * 2;

    for (int k0 = 0; k0 < K; k0 += 8) {
        float2 av = make_float2(0.f, 0.f);
        int arow = rowBase + a_m;
        if (arow < M) av = *(const float2*)(A + (size_t)arow * K + k0 + a_k);
        As[a_k][a_m] = av.x;
        As[a_k + 1][a_m] = av.y;
        float2 bv = *(const float2*)(B + (size_t)(k0 + b_k) * Ncol + colBase + b_n);
        Bs[b_k][b_n] = bv.x;
        Bs[b_k][b_n + 1] = bv.y;
        __syncthreads();
#pragma unroll
        for (int kk = 0; kk < 8; kk++) {
            float a[4], b[4];
#pragma unroll
            for (int i = 0; i < 4; i++) a[i] = As[kk][ty * 4 + i];
#pragma unroll
            for (int j = 0; j < 4; j++) b[j] = Bs[kk][tx * 4 + j];
#pragma unroll
            for (int i = 0; i < 4; i++)
#pragma unroll
                for (int j = 0; j < 4; j++) acc[i][j] += a[i] * b[j];
        }
        __syncthreads();
    }
#pragma unroll
    for (int i = 0; i < 4; i++) {
        int row = rowBase + ty * 4 + i;
        if (row < M) {
            float4 v = make_float4(acc[i][0], acc[i][1], acc[i][2], acc[i][3]);
            *(float4*)(C + (size_t)row * Ncol + colBase + tx * 4) = v;
        }
    }
}

// ---------------- attention logits: warp per (node, head), reads g_bufA ----------------
__global__ void k_logits(const float* __restrict__ att_src,
                         const float* __restrict__ att_dst) {
    int wid = (blockIdx.x * blockDim.x + threadIdx.x) >> 5;
    int lane = threadIdx.x & 31;
    if (wid >= NN * HEADS) return;
    int n = wid >> 2, head = wid & 3;
    float2 hv = *(const float2*)(g_bufA + (size_t)n * D1 + head * HID + lane * 2);
    float2 as = *(const float2*)(att_src + head * HID + lane * 2);
    float2 ad = *(const float2*)(att_dst + head * HID + lane * 2);
    float ds = hv.x * as.x + hv.y * as.y;
    float dd = hv.x * ad.x + hv.y * ad.y;
#pragma unroll
    for (int off = 16; off > 0; off >>= 1) {
        ds += __shfl_xor_sync(0xffffffffu, ds, off);
        dd += __shfl_xor_sync(0xffffffffu, dd, off);
    }
    if (lane == 0) {
        g_as[n * HEADS + head] = ds;
        g_ad[n * HEADS + head] = dd;
    }
}

// ---------------- aggregation: warp per node, ALL 4 heads ----------------
// lane l owns dims [8l, 8l+8) of the 256-wide row; head = l>>3.
// softmax without running max (logit range is tiny: |e| << 88, shift-invariant).
// reads g_bufA (h) + g_as/g_ad + CSR, writes g_bufB (with bias + ELU)
__global__ void k_agg(const float* __restrict__ bias) {
    int wid = (blockIdx.x * blockDim.x + threadIdx.x) >> 5;
    int lane = threadIdx.x & 31;
    if (wid >= NN) return;
    int n = wid;
    int head = lane >> 3;
    int beg = g_rowptr[n], end = g_rowptr[n + 1];
    float adv = g_ad[n * HEADS + head];

    const float4* __restrict__ hbase = (const float4*)g_bufA;
    // lane's two float4 within a row: indices lane*2, lane*2+1 (row = 64 float4)
    float s = 0.f;
    float4 a0 = make_float4(0.f, 0.f, 0.f, 0.f);
    float4 a1 = make_float4(0.f, 0.f, 0.f, 0.f);

    for (int p = beg; p < end; p++) {
        int sn = g_csr[p];
        float e = g_as[sn * HEADS + head] + adv;
        e = (e > 0.f) ? e : NEG_SLOPE * e;
        float w = __expf(e);
        const float4* r = hbase + (size_t)sn * (D1 / 4) + lane * 2;
        float4 h0 = r[0];
        float4 h1 = r[1];
        s += w;
        a0.x = fmaf(w, h0.x, a0.x); a0.y = fmaf(w, h0.y, a0.y);
        a0.z = fmaf(w, h0.z, a0.z); a0.w = fmaf(w, h0.w, a0.w);
        a1.x = fmaf(w, h1.x, a1.x); a1.y = fmaf(w, h1.y, a1.y);
        a1.z = fmaf(w, h1.z, a1.z); a1.w = fmaf(w, h1.w, a1.w);
    }
    float inv = 1.f / s;
    const float4* bptr = (const float4*)bias + lane * 2;
    float4 b0 = bptr[0], b1 = bptr[1];
    float o[8];
    o[0] = a0.x * inv + b0.x; o[1] = a0.y * inv + b0.y;
    o[2] = a0.z * inv + b0.z; o[3] = a0.w * inv + b0.w;
    o[4] = a1.x * inv + b1.x; o[5] = a1.y * inv + b1.y;
    o[6] = a1.z * inv + b1.z; o[7] = a1.w * inv + b1.w;
#pragma unroll
    for (int j = 0; j < 8; j++) o[j] = (o[j] > 0.f) ? o[j] : expm1f(o[j]);
    float4* w0 = (float4*)g_bufB + (size_t)n * (D1 / 4) + lane * 2;
    w0[0] = make_float4(o[0], o[1], o[2], o[3]);
    w0[1] = make_float4(o[4], o[5], o[6], o[7]);
}

// ---------------- global mean pool (batch sorted int32), reads g_bufB ----------------
__device__ int lower_bound_i(const int* a, int n, int v) {
    int lo = 0, hi = n;
    while (lo < hi) {
        int mid = (lo + hi) >> 1;
        if (a[mid] < v) lo = mid + 1; else hi = mid;
    }
    return lo;
}

__global__ void k_pool(const int* __restrict__ batch) {
    __shared__ int s_lo, s_hi;
    int g = blockIdx.x;
    int tid = threadIdx.x;
    if (tid == 0) {
        s_lo = lower_bound_i(batch, NN, g);
        s_hi = lower_bound_i(batch, NN, g + 1);
    }
    __syncthreads();
    int lo = s_lo, hi = s_hi;
    float acc = 0.f;
    for (int n = lo; n < hi; n++) acc += g_bufB[(size_t)n * D1 + tid];
    float cnt = (float)(hi - lo);
    g_pooled[g * D1 + tid] = acc / fmaxf(cnt, 1.f);
}

// ---------------- final linear ----------------
__global__ void k_fc(const float* __restrict__ fc_w, const float* __restrict__ fc_b,
                     float* __restrict__ out) {
    __shared__ float sp[D1];
    int g = blockIdx.x;
    int tid = threadIdx.x;  // 64 threads
    for (int i = tid; i < D1; i += 64) sp[i] = g_pooled[g * D1 + i];
    __syncthreads();
    float acc = fc_b[tid];
#pragma unroll 8
    for (int k = 0; k < D1; k++) acc += sp[k] * fc_w[k * OUT_F + tid];
    out[g * OUT_F + tid] = acc;
}

// ---------------- launch (pure kernel launches; no runtime APIs) ----------------
extern "C" void kernel_launch(void* const* d_in, const int* in_sizes, int n_in,
                              void* d_out, int out_size) {
    const float* x        = (const float*)d_in[0];
    const int*   ei       = (const int*)d_in[1];     // int64 in reference -> int32 in harness
    const int*   bat      = (const int*)d_in[2];     // int64 in reference -> int32 in harness
    const float* W1       = (const float*)d_in[3];
    const float* att_src1 = (const float*)d_in[4];
    const float* att_dst1 = (const float*)d_in[5];
    const float* b1       = (const float*)d_in[6];
    const float* W2       = (const float*)d_in[7];
    const float* att_src2 = (const float*)d_in[8];
    const float* att_dst2 = (const float*)d_in[9];
    const float* b2       = (const float*)d_in[10];
    const float* fc_w     = (const float*)d_in[11];
    const float* fc_b     = (const float*)d_in[12];
    float* out = (float*)d_out;

    const int ZB = 256;
    // CSR build
    k_zero<<<196, ZB>>>();
    k_hist<<<(ET + ZB - 1) / ZB, ZB>>>(ei);
    int nb = (NN + 4095) / 4096;  // 13
    k_scan_part<<<nb, 1024>>>();
    k_scan_sums<<<1, 32>>>(nb);
    k_scan_add<<<(NN + ZB - 1) / ZB, ZB>>>();
    k_fill_csr<<<(ET + ZB - 1) / ZB, ZB>>>(ei);

    dim3 ggrid(D1 / 64, (NN + 63) / 64);
    int logitBlocks = (NN * HEADS * 32 + 255) / 256;  // warp per (node, head)
    int aggBlocks   = (NN * 32 + 255) / 256;          // warp per node

    // layer 1: x -> g_bufA -> (logits) -> agg+ELU -> g_bufB
    k_gemm<<<ggrid, 256>>>(x, W1, 1, NN, F_IN, D1);
    k_logits<<<logitBlocks, 256>>>(att_src1, att_dst1);
    k_agg<<<aggBlocks, 256>>>(b1);

    // layer 2: g_bufB -> g_bufA -> (logits) -> agg+ELU -> g_bufB
    k_gemm<<<ggrid, 256>>>(nullptr, W2, 0, NN, D1, D1);
    k_logits<<<logitBlocks, 256>>>(att_src2, att_dst2);
    k_agg<<<aggBlocks, 256>>>(b2);

    // pool + fc
    k_pool<<<NGRAPH, D1>>>(bat);
    k_fc<<<NGRAPH, OUT_F>>>(fc_w, fc_b, out);
}

// round 16
// speedup vs baseline: 1.5169x; 1.2430x over previous
#include <cuda_runtime.h>
#include <cuda_bf16.h>
#include <math.h>
#include <stdint.h>

#define NN      50000
#define MPAD    50176            // 392 * 128
#define EE      800000
#define ET      (EE + NN)        // edges + self loops
#define F_IN    128
#define HID     64
#define HEADS   4
#define D1      (HID * HEADS)    // 256
#define OUT_F   64
#define NGRAPH  512
#define NEG_SLOPE 0.2f

// ---------------- scratch (static device globals; no runtime alloc) ----------------
__device__ float g_bufA[NN * D1];               // 51.2 MB (GEMM output h)
__device__ float g_bufB[NN * D1];               // 51.2 MB (layer output after agg+ELU)
__device__ __nv_bfloat16 g_a3[MPAD * 3 * D1];   // 77 MB  (split-A, K3 up to 768)
__device__ __nv_bfloat16 g_w3[D1 * 3 * D1];     // 0.4 MB (split-transposed W)
__device__ float g_as[NN * HEADS];
__device__ float g_ad[NN * HEADS];
__device__ int   g_deg[NN];
__device__ int   g_fill[NN];
__device__ int   g_tmp[NN];
__device__ int   g_rowptr[NN + 1];
__device__ int   g_csr[ET];
__device__ int   g_blocksum[64];
__device__ int   g_blockoff[64];
__device__ float g_pooled[NGRAPH * D1];

__device__ __forceinline__ uint32_t smem_u32(const void* p) {
    uint32_t a;
    asm("{ .reg .u64 t; cvta.to.shared.u64 t, %1; cvt.u32.u64 %0, t; }" : "=r"(a) : "l"(p));
    return a;
}

// ---------------- CSR build ----------------
__global__ void k_zero() {
    for (int i = blockIdx.x * blockDim.x + threadIdx.x; i < NN; i += gridDim.x * blockDim.x) {
        g_deg[i] = 0;
        g_fill[i] = 0;
    }
}

__global__ void k_hist(const int* __restrict__ ei) {
    int i = blockIdx.x * blockDim.x + threadIdx.x;
    if (i >= ET) return;
    int d = (i < EE) ? ei[EE + i] : (i - EE);
    atomicAdd(&g_deg[d], 1);
}

__global__ void k_scan_part() {
    __shared__ int sh[1024];
    int tid = threadIdx.x;
    int idx0 = blockIdx.x * 4096 + tid * 4;
    int v[4];
    int s = 0;
#pragma unroll
    for (int j = 0; j < 4; j++) {
        v[j] = (idx0 + j < NN) ? g_deg[idx0 + j] : 0;
        s += v[j];
    }
    sh[tid] = s;
    __syncthreads();
    for (int off = 1; off < 1024; off <<= 1) {
        int t = (tid >= off) ? sh[tid - off] : 0;
        __syncthreads();
        sh[tid] += t;
        __syncthreads();
    }
    int run = sh[tid] - s;
#pragma unroll
    for (int j = 0; j < 4; j++) {
        run += v[j];
        if (idx0 + j < NN) g_tmp[idx0 + j] = run;
    }
    if (tid == 1023) g_blocksum[blockIdx.x] = sh[1023];
}

__global__ void k_scan_sums(int nb) {
    if (threadIdx.x == 0 && blockIdx.x == 0) {
        int run = 0;
        for (int b = 0; b < nb; b++) {
            int t = g_blocksum[b];
            g_blockoff[b] = run;
            run += t;
        }
    }
}

__global__ void k_scan_add() {
    int i = blockIdx.x * blockDim.x + threadIdx.x;
    if (i >= NN) return;
    g_rowptr[i + 1] = g_tmp[i] + g_blockoff[i >> 12];
    if (i == 0) g_rowptr[0] = 0;
}

__global__ void k_fill_csr(const int* __restrict__ ei) {
    int i = blockIdx.x * blockDim.x + threadIdx.x;
    if (i >= ET) return;
    int s, d;
    if (i < EE) { s = ei[i]; d = ei[EE + i]; }
    else        { s = d = i - EE; }
    int pos = g_rowptr[d] + atomicAdd(&g_fill[d], 1);
    g_csr[pos] = s;
}

// ---------------- bf16x3 split conversions ----------------
// A' [MPAD, 3K]: blocks [hi | lo | hi]. src = ext (x) if useExt, else g_bufB.
__global__ void k_split_a(const float* __restrict__ srcExt, int useExt, int kbits) {
    const float* __restrict__ src = useExt ? srcExt : (const float*)g_bufB;
    int K = 1 << kbits;
    long long idx = (long long)blockIdx.x * blockDim.x + threadIdx.x;
    if (idx >= (long long)MPAD << kbits) return;
    int m = (int)(idx >> kbits);
    int k = (int)(idx & (K - 1));
    float a = (m < NN) ? src[(size_t)m * K + k] : 0.f;
    __nv_bfloat16 hi = __float2bfloat16(a);
    __nv_bfloat16 lo = __float2bfloat16(a - __bfloat162float(hi));
    __nv_bfloat16* dst = g_a3 + (size_t)m * (3 * K);
    dst[k] = hi;
    dst[K + k] = lo;
    dst[2 * K + k] = hi;
}

// B' [256, 3K] (transposed W): blocks along k = [hi | hi | lo].  W is [K, 256].
__global__ void k_split_w(const float* __restrict__ W, int kbits) {
    int K = 1 << kbits;
    int idx = blockIdx.x * blockDim.x + threadIdx.x;
    if (idx >= (D1 << kbits)) return;
    int n = idx >> kbits;
    int k = idx & (K - 1);
    float w = W[(size_t)k * D1 + n];
    __nv_bfloat16 hi = __float2bfloat16(w);
    __nv_bfloat16 lo = __float2bfloat16(w - __bfloat162float(hi));
    __nv_bfloat16* dst = g_w3 + (size_t)n * (3 * K);
    dst[k] = hi;
    dst[K + k] = hi;
    dst[2 * K + k] = lo;
}

// ---------------- mma.sync bf16 GEMM: g_bufA[M,256] = A'[MPAD,K3] @ B'[256,K3]^T ----------------
// CTA tile 128(m) x 128(n), 8 warps in 4x2 (m x n): warp tile 32 x 64.
// K chunks of 64 bf16 in smem, stride 72 bf16 (144 B, conflict-free ldmatrix).
#define SAK 72
__global__ void __launch_bounds__(256, 2) k_gemm_mma(int K3) {
    __shared__ __nv_bfloat16 sA[128 * SAK];
    __shared__ __nv_bfloat16 sB[128 * SAK];

    int tid = threadIdx.x;
    int wid = tid >> 5, lane = tid & 31;
    int wm = wid & 3, wn = wid >> 2;       // warp coords: m 0..3, n 0..1
    int tileM = blockIdx.y * 128;
    int nBase = blockIdx.x * 128;

    uint32_t sA_u = smem_u32(sA);
    uint32_t sB_u = smem_u32(sB);

    const __nv_bfloat16* Abase = g_a3 + (size_t)tileM * K3;
    const __nv_bfloat16* Bbase = g_w3 + (size_t)nBase * K3;

    float acc[2][8][4] = {};

    // precomputed ldmatrix lane addresses (within-chunk col added per k-step)
    // A: row = wm*32 + t*16 + (lane&15), colofs = (lane>>4)*8
    int a_row_l = wm * 32 + (lane & 15);
    int a_col_l = (lane >> 4) * 8;
    // B: row = wn*64 + j*16 + (lane>>4)*8 + (lane&7)  [j = n-pair index 0..3]
    int b_row_l = wn * 64 + (lane >> 4) * 8 + (lane & 7);
    int b_col_l = ((lane >> 3) & 1) * 8;

    int nch = K3 >> 6;
    for (int c = 0; c < nch; c++) {
        // fill smem: 128 rows x 64 bf16 = 1024 uint4 per tile, 4 per thread per tile
#pragma unroll
        for (int i = 0; i < 4; i++) {
            int p = tid + i * 256;
            int row = p >> 3, seg = p & 7;
            *(uint4*)(sA + row * SAK + seg * 8) =
                *(const uint4*)(Abase + (size_t)row * K3 + c * 64 + seg * 8);
            *(uint4*)(sB + row * SAK + seg * 8) =
                *(const uint4*)(Bbase + (size_t)row * K3 + c * 64 + seg * 8);
        }
        __syncthreads();

#pragma unroll
        for (int ks = 0; ks < 4; ks++) {
            uint32_t a[2][4];
#pragma unroll
            for (int t = 0; t < 2; t++) {
                uint32_t addr = sA_u + (uint32_t)(((a_row_l + t * 16) * SAK) + ks * 16 + a_col_l) * 2;
                asm volatile("ldmatrix.sync.aligned.m8n8.x4.shared.b16 {%0,%1,%2,%3}, [%4];"
                             : "=r"(a[t][0]), "=r"(a[t][1]), "=r"(a[t][2]), "=r"(a[t][3])
                             : "r"(addr));
            }
            uint32_t b[8][2];
#pragma unroll
            for (int j = 0; j < 4; j++) {
                uint32_t addr = sB_u + (uint32_t)(((b_row_l + j * 16) * SAK) + ks * 16 + b_col_l) * 2;
                asm volatile("ldmatrix.sync.aligned.m8n8.x4.shared.b16 {%0,%1,%2,%3}, [%4];"
                             : "=r"(b[2 * j][0]), "=r"(b[2 * j][1]),
                               "=r"(b[2 * j + 1][0]), "=r"(b[2 * j + 1][1])
                             : "r"(addr));
            }
#pragma unroll
            for (int t = 0; t < 2; t++)
#pragma unroll
                for (int j = 0; j < 8; j++) {
                    asm volatile(
                        "mma.sync.aligned.m16n8k16.row.col.f32.bf16.bf16.f32 "
                        "{%0,%1,%2,%3}, {%4,%5,%6,%7}, {%8,%9}, {%0,%1,%2,%3};"
                        : "+f"(acc[t][j][0]), "+f"(acc[t][j][1]),
                          "+f"(acc[t][j][2]), "+f"(acc[t][j][3])
                        : "r"(a[t][0]), "r"(a[t][1]), "r"(a[t][2]), "r"(a[t][3]),
                          "r"(b[j][0]), "r"(b[j][1]));
                }
        }
        __syncthreads();
    }

    // epilogue: c0,c1 -> row m0+(lane>>2); c2,c3 -> row +8; cols n0 + (lane&3)*2
    int gq = lane >> 2, tig = lane & 3;
#pragma unroll
    for (int t = 0; t < 2; t++) {
        int r0 = tileM + wm * 32 + t * 16 + gq;
#pragma unroll
        for (int j = 0; j < 8; j++) {
            int col = nBase + wn * 64 + j * 8 + tig * 2;
            if (r0 < NN)
                *(float2*)(g_bufA + (size_t)r0 * D1 + col) = make_float2(acc[t][j][0], acc[t][j][1]);
            if (r0 + 8 < NN)
                *(float2*)(g_bufA + (size_t)(r0 + 8) * D1 + col) = make_float2(acc[t][j][2], acc[t][j][3]);
        }
    }
}

// ---------------- attention logits: warp per (node, head), reads g_bufA ----------------
__global__ void k_logits(const float* __restrict__ att_src,
                         const float* __restrict__ att_dst) {
    int wid = (blockIdx.x * blockDim.x + threadIdx.x) >> 5;
    int lane = threadIdx.x & 31;
    if (wid >= NN * HEADS) return;
    int n = wid >> 2, head = wid & 3;
    float2 hv = *(const float2*)(g_bufA + (size_t)n * D1 + head * HID + lane * 2);
    float2 as = *(const float2*)(att_src + head * HID + lane * 2);
    float2 ad = *(const float2*)(att_dst + head * HID + lane * 2);
    float ds = hv.x * as.x + hv.y * as.y;
    float dd = hv.x * ad.x + hv.y * ad.y;
#pragma unroll
    for (int off = 16; off > 0; off >>= 1) {
        ds += __shfl_xor_sync(0xffffffffu, ds, off);
        dd += __shfl_xor_sync(0xffffffffu, dd, off);
    }
    if (lane == 0) {
        g_as[n * HEADS + head] = ds;
        g_ad[n * HEADS + head] = dd;
    }
}

// ---------------- aggregation: warp per node, ALL 4 heads (no-max softmax) ----------------
__global__ void k_agg(const float* __restrict__ bias) {
    int wid = (blockIdx.x * blockDim.x + threadIdx.x) >> 5;
    int lane = threadIdx.x & 31;
    if (wid >= NN) return;
    int n = wid;
    int head = lane >> 3;
    int beg = g_rowptr[n], end = g_rowptr[n + 1];
    float adv = g_ad[n * HEADS + head];

    const float4* __restrict__ hbase = (const float4*)g_bufA;
    float s = 0.f;
    float4 a0 = make_float4(0.f, 0.f, 0.f, 0.f);
    float4 a1 = make_float4(0.f, 0.f, 0.f, 0.f);

    for (int p = beg; p < end; p++) {
        int sn = g_csr[p];
        float e = g_as[sn * HEADS + head] + adv;
        e = (e > 0.f) ? e : NEG_SLOPE * e;
        float w = __expf(e);
        const float4* r = hbase + (size_t)sn * (D1 / 4) + lane * 2;
        float4 h0 = r[0];
        float4 h1 = r[1];
        s += w;
        a0.x = fmaf(w, h0.x, a0.x); a0.y = fmaf(w, h0.y, a0.y);
        a0.z = fmaf(w, h0.z, a0.z); a0.w = fmaf(w, h0.w, a0.w);
        a1.x = fmaf(w, h1.x, a1.x); a1.y = fmaf(w, h1.y, a1.y);
        a1.z = fmaf(w, h1.z, a1.z); a1.w = fmaf(w, h1.w, a1.w);
    }
    float inv = 1.f / s;
    const float4* bptr = (const float4*)bias + lane * 2;
    float4 b0 = bptr[0], b1 = bptr[1];
    float o[8];
    o[0] = a0.x * inv + b0.x; o[1] = a0.y * inv + b0.y;
    o[2] = a0.z * inv + b0.z; o[3] = a0.w * inv + b0.w;
    o[4] = a1.x * inv + b1.x; o[5] = a1.y * inv + b1.y;
    o[6] = a1.z * inv + b1.z; o[7] = a1.w * inv + b1.w;
#pragma unroll
    for (int j = 0; j < 8; j++) o[j] = (o[j] > 0.f) ? o[j] : expm1f(o[j]);
    float4* w0 = (float4*)g_bufB + (size_t)n * (D1 / 4) + lane * 2;
    w0[0] = make_float4(o[0], o[1], o[2], o[3]);
    w0[1] = make_float4(o[4], o[5], o[6], o[7]);
}

// ---------------- global mean pool (batch sorted int32), reads g_bufB ----------------
__device__ int lower_bound_i(const int* a, int n, int v) {
    int lo = 0, hi = n;
    while (lo < hi) {
        int mid = (lo + hi) >> 1;
        if (a[mid] < v) lo = mid + 1; else hi = mid;
    }
    return lo;
}

__global__ void k_pool(const int* __restrict__ batch) {
    __shared__ int s_lo, s_hi;
    int g = blockIdx.x;
    int tid = threadIdx.x;
    if (tid == 0) {
        s_lo = lower_bound_i(batch, NN, g);
        s_hi = lower_bound_i(batch, NN, g + 1);
    }
    __syncthreads();
    int lo = s_lo, hi = s_hi;
    float acc = 0.f;
    for (int n = lo; n < hi; n++) acc += g_bufB[(size_t)n * D1 + tid];
    float cnt = (float)(hi - lo);
    g_pooled[g * D1 + tid] = acc / fmaxf(cnt, 1.f);
}

// ---------------- final linear ----------------
__global__ void k_fc(const float* __restrict__ fc_w, const float* __restrict__ fc_b,
                     float* __restrict__ out) {
    __shared__ float sp[D1];
    int g = blockIdx.x;
    int tid = threadIdx.x;  // 64 threads
    for (int i = tid; i < D1; i += 64) sp[i] = g_pooled[g * D1 + i];
    __syncthreads();
    float acc = fc_b[tid];
#pragma unroll 8
    for (int k = 0; k < D1; k++) acc += sp[k] * fc_w[k * OUT_F + tid];
    out[g * OUT_F + tid] = acc;
}

// ---------------- launch (pure kernel launches; no runtime APIs) ----------------
extern "C" void kernel_launch(void* const* d_in, const int* in_sizes, int n_in,
                              void* d_out, int out_size) {
    const float* x        = (const float*)d_in[0];
    const int*   ei       = (const int*)d_in[1];
    const int*   bat      = (const int*)d_in[2];
    const float* W1       = (const float*)d_in[3];
    const float* att_src1 = (const float*)d_in[4];
    const float* att_dst1 = (const float*)d_in[5];
    const float* b1       = (const float*)d_in[6];
    const float* W2       = (const float*)d_in[7];
    const float* att_src2 = (const float*)d_in[8];
    const float* att_dst2 = (const float*)d_in[9];
    const float* b2       = (const float*)d_in[10];
    const float* fc_w     = (const float*)d_in[11];
    const float* fc_b     = (const float*)d_in[12];
    float* out = (float*)d_out;

    const int ZB = 256;
    // CSR build
    k_zero<<<196, ZB>>>();
    k_hist<<<(ET + ZB - 1) / ZB, ZB>>>(ei);
    int nb = (NN + 4095) / 4096;  // 13
    k_scan_part<<<nb, 1024>>>();
    k_scan_sums<<<1, 32>>>(nb);
    k_scan_add<<<(NN + ZB - 1) / ZB, ZB>>>();
    k_fill_csr<<<(ET + ZB - 1) / ZB, ZB>>>(ei);

    dim3 tcgrid(2, MPAD / 128);                       // (nTiles, mTiles) = (2, 392)
    int logitBlocks = (NN * HEADS * 32 + 255) / 256;
    int aggBlocks   = (NN * 32 + 255) / 256;

    // layer 1: K = 128 (kbits 7), K3 = 384
    k_split_w<<<(D1 << 7) / ZB, ZB>>>(W1, 7);
    k_split_a<<<(int)(((long long)MPAD << 7) / ZB), ZB>>>(x, 1, 7);
    k_gemm_mma<<<tcgrid, 256>>>(384);
    k_logits<<<logitBlocks, 256>>>(att_src1, att_dst1);
    k_agg<<<aggBlocks, 256>>>(b1);

    // layer 2: K = 256 (kbits 8), K3 = 768
    k_split_w<<<(D1 << 8) / ZB, ZB>>>(W2, 8);
    k_split_a<<<(int)(((long long)MPAD << 8) / ZB), ZB>>>(nullptr, 0, 8);
    k_gemm_mma<<<tcgrid, 256>>>(768);
    k_logits<<<logitBlocks, 256>>>(att_src2, att_dst2);
    k_agg<<<aggBlocks, 256>>>(b2);

    // pool + fc
    k_pool<<<NGRAPH, D1>>>(bat);
    k_fc<<<NGRAPH, OUT_F>>>(fc_w, fc_b, out);
}

// round 17
// speedup vs baseline: 1.8373x; 1.2112x over previous
#include <cuda_runtime.h>
#include <cuda_bf16.h>
#include <cuda_fp16.h>
#include <math.h>
#include <stdint.h>

#define NN      50000
#define MPAD    50176            // 392 * 128
#define EE      800000
#define ET      (EE + NN)        // edges + self loops
#define F_IN    128
#define HID     64
#define HEADS   4
#define D1      (HID * HEADS)    // 256
#define OUT_F   64
#define NGRAPH  512
#define NEG_SLOPE 0.2f

// ---------------- scratch (static device globals; no runtime alloc) ----------------
__device__ float g_bufB[NN * D1];               // 51.2 MB (layer-2 output for pool)
__device__ __half g_h16[NN * D1];               // 25.6 MB (h in fp16 for logits+agg gather)
__device__ __nv_bfloat16 g_a3[MPAD * 3 * D1];   // 77 MB  (split-A, K3 up to 768)
__device__ __nv_bfloat16 g_w3[D1 * 3 * D1];     // 0.4 MB (split-transposed W)
__device__ float g_as[NN * HEADS];
__device__ float g_ad[NN * HEADS];
__device__ int   g_deg[NN];
__device__ int   g_fill[NN];
__device__ int   g_tmp[NN];
__device__ int   g_rowptr[NN + 1];
__device__ int   g_csr[ET];
__device__ int   g_blocksum[64];
__device__ int   g_blockoff[64];
__device__ float g_pooled[NGRAPH * D1];

__device__ __forceinline__ uint32_t smem_u32(const void* p) {
    uint32_t a;
    asm("{ .reg .u64 t; cvta.to.shared.u64 t, %1; cvt.u32.u64 %0, t; }" : "=r"(a) : "l"(p));
    return a;
}

// ---------------- CSR build ----------------
__global__ void k_zero() {
    for (int i = blockIdx.x * blockDim.x + threadIdx.x; i < NN; i += gridDim.x * blockDim.x) {
        g_deg[i] = 0;
        g_fill[i] = 0;
    }
}

__global__ void k_hist(const int* __restrict__ ei) {
    int i = blockIdx.x * blockDim.x + threadIdx.x;
    if (i >= ET) return;
    int d = (i < EE) ? ei[EE + i] : (i - EE);
    atomicAdd(&g_deg[d], 1);
}

__global__ void k_scan_part() {
    __shared__ int sh[1024];
    int tid = threadIdx.x;
    int idx0 = blockIdx.x * 4096 + tid * 4;
    int v[4];
    int s = 0;
#pragma unroll
    for (int j = 0; j < 4; j++) {
        v[j] = (idx0 + j < NN) ? g_deg[idx0 + j] : 0;
        s += v[j];
    }
    sh[tid] = s;
    __syncthreads();
    for (int off = 1; off < 1024; off <<= 1) {
        int t = (tid >= off) ? sh[tid - off] : 0;
        __syncthreads();
        sh[tid] += t;
        __syncthreads();
    }
    int run = sh[tid] - s;
#pragma unroll
    for (int j = 0; j < 4; j++) {
        run += v[j];
        if (idx0 + j < NN) g_tmp[idx0 + j] = run;
    }
    if (tid == 1023) g_blocksum[blockIdx.x] = sh[1023];
}

__global__ void k_scan_sums(int nb) {
    if (threadIdx.x == 0 && blockIdx.x == 0) {
        int run = 0;
        for (int b = 0; b < nb; b++) {
            int t = g_blocksum[b];
            g_blockoff[b] = run;
            run += t;
        }
    }
}

__global__ void k_scan_add() {
    int i = blockIdx.x * blockDim.x + threadIdx.x;
    if (i >= NN) return;
    g_rowptr[i + 1] = g_tmp[i] + g_blockoff[i >> 12];
    if (i == 0) g_rowptr[0] = 0;
}

__global__ void k_fill_csr(const int* __restrict__ ei) {
    int i = blockIdx.x * blockDim.x + threadIdx.x;
    if (i >= ET) return;
    int s, d;
    if (i < EE) { s = ei[i]; d = ei[EE + i]; }
    else        { s = d = i - EE; }
    int pos = g_rowptr[d] + atomicAdd(&g_fill[d], 1);
    g_csr[pos] = s;
}

// ---------------- bf16x3 split conversions ----------------
// A' [MPAD, 3K]: blocks [hi | lo | hi] from external fp32 src (layer 1 only).
__global__ void k_split_a(const float* __restrict__ src, int kbits) {
    int K = 1 << kbits;
    long long idx = (long long)blockIdx.x * blockDim.x + threadIdx.x;
    if (idx >= (long long)MPAD << kbits) return;
    int m = (int)(idx >> kbits);
    int k = (int)(idx & (K - 1));
    float a = (m < NN) ? src[(size_t)m * K + k] : 0.f;
    __nv_bfloat16 hi = __float2bfloat16(a);
    __nv_bfloat16 lo = __float2bfloat16(a - __bfloat162float(hi));
    __nv_bfloat16* dst = g_a3 + (size_t)m * (3 * K);
    dst[k] = hi;
    dst[K + k] = lo;
    dst[2 * K + k] = hi;
}

// B' [256, 3K] (transposed W): blocks along k = [hi | hi | lo].  W is [K, 256].
__global__ void k_split_w(const float* __restrict__ W, int kbits) {
    int K = 1 << kbits;
    int idx = blockIdx.x * blockDim.x + threadIdx.x;
    if (idx >= (D1 << kbits)) return;
    int n = idx >> kbits;
    int k = idx & (K - 1);
    float w = W[(size_t)k * D1 + n];
    __nv_bfloat16 hi = __float2bfloat16(w);
    __nv_bfloat16 lo = __float2bfloat16(w - __bfloat162float(hi));
    __nv_bfloat16* dst = g_w3 + (size_t)n * (3 * K);
    dst[k] = hi;
    dst[K + k] = hi;
    dst[2 * K + k] = lo;
}

// ---------------- mma.sync bf16 GEMM: g_h16[M,256] = A'[MPAD,K3] @ B'[256,K3]^T ----------------
// CTA tile 128(m) x 128(n), 8 warps in 4x2 (m x n): warp tile 32 x 64.
// K chunks of 64 bf16 in smem, stride 72 bf16 (144 B, conflict-free ldmatrix).
#define SAK 72
__global__ void __launch_bounds__(256, 2) k_gemm_mma(int K3) {
    __shared__ __nv_bfloat16 sA[128 * SAK];
    __shared__ __nv_bfloat16 sB[128 * SAK];

    int tid = threadIdx.x;
    int wid = tid >> 5, lane = tid & 31;
    int wm = wid & 3, wn = wid >> 2;
    int tileM = blockIdx.y * 128;
    int nBase = blockIdx.x * 128;

    uint32_t sA_u = smem_u32(sA);
    uint32_t sB_u = smem_u32(sB);

    const __nv_bfloat16* Abase = g_a3 + (size_t)tileM * K3;
    const __nv_bfloat16* Bbase = g_w3 + (size_t)nBase * K3;

    float acc[2][8][4] = {};

    int a_row_l = wm * 32 + (lane & 15);
    int a_col_l = (lane >> 4) * 8;
    int b_row_l = wn * 64 + (lane >> 4) * 8 + (lane & 7);
    int b_col_l = ((lane >> 3) & 1) * 8;

    int nch = K3 >> 6;
    for (int c = 0; c < nch; c++) {
#pragma unroll
        for (int i = 0; i < 4; i++) {
            int p = tid + i * 256;
            int row = p >> 3, seg = p & 7;
            *(uint4*)(sA + row * SAK + seg * 8) =
                *(const uint4*)(Abase + (size_t)row * K3 + c * 64 + seg * 8);
            *(uint4*)(sB + row * SAK + seg * 8) =
                *(const uint4*)(Bbase + (size_t)row * K3 + c * 64 + seg * 8);
        }
        __syncthreads();

#pragma unroll
        for (int ks = 0; ks < 4; ks++) {
            uint32_t a[2][4];
#pragma unroll
            for (int t = 0; t < 2; t++) {
                uint32_t addr = sA_u + (uint32_t)(((a_row_l + t * 16) * SAK) + ks * 16 + a_col_l) * 2;
                asm volatile("ldmatrix.sync.aligned.m8n8.x4.shared.b16 {%0,%1,%2,%3}, [%4];"
                             : "=r"(a[t][0]), "=r"(a[t][1]), "=r"(a[t][2]), "=r"(a[t][3])
                             : "r"(addr));
            }
            uint32_t b[8][2];
#pragma unroll
            for (int j = 0; j < 4; j++) {
                uint32_t addr = sB_u + (uint32_t)(((b_row_l + j * 16) * SAK) + ks * 16 + b_col_l) * 2;
                asm volatile("ldmatrix.sync.aligned.m8n8.x4.shared.b16 {%0,%1,%2,%3}, [%4];"
                             : "=r"(b[2 * j][0]), "=r"(b[2 * j][1]),
                               "=r"(b[2 * j + 1][0]), "=r"(b[2 * j + 1][1])
                             : "r"(addr));
            }
#pragma unroll
            for (int t = 0; t < 2; t++)
#pragma unroll
                for (int j = 0; j < 8; j++) {
                    asm volatile(
                        "mma.sync.aligned.m16n8k16.row.col.f32.bf16.bf16.f32 "
                        "{%0,%1,%2,%3}, {%4,%5,%6,%7}, {%8,%9}, {%0,%1,%2,%3};"
                        : "+f"(acc[t][j][0]), "+f"(acc[t][j][1]),
                          "+f"(acc[t][j][2]), "+f"(acc[t][j][3])
                        : "r"(a[t][0]), "r"(a[t][1]), "r"(a[t][2]), "r"(a[t][3]),
                          "r"(b[j][0]), "r"(b[j][1]));
                }
        }
        __syncthreads();
    }

    // epilogue -> fp16 h
    int gq = lane >> 2, tig = lane & 3;
#pragma unroll
    for (int t = 0; t < 2; t++) {
        int r0 = tileM + wm * 32 + t * 16 + gq;
#pragma unroll
        for (int j = 0; j < 8; j++) {
            int col = nBase + wn * 64 + j * 8 + tig * 2;
            if (r0 < NN)
                *(__half2*)(g_h16 + (size_t)r0 * D1 + col) =
                    __floats2half2_rn(acc[t][j][0], acc[t][j][1]);
            if (r0 + 8 < NN)
                *(__half2*)(g_h16 + (size_t)(r0 + 8) * D1 + col) =
                    __floats2half2_rn(acc[t][j][2], acc[t][j][3]);
        }
    }
}

// ---------------- attention logits: warp per (node, head), reads g_h16 ----------------
__global__ void k_logits(const float* __restrict__ att_src,
                         const float* __restrict__ att_dst) {
    int wid = (blockIdx.x * blockDim.x + threadIdx.x) >> 5;
    int lane = threadIdx.x & 31;
    if (wid >= NN * HEADS) return;
    int n = wid >> 2, head = wid & 3;
    float2 hv = __half22float2(*(const __half2*)(g_h16 + (size_t)n * D1 + head * HID + lane * 2));
    float2 as = *(const float2*)(att_src + head * HID + lane * 2);
    float2 ad = *(const float2*)(att_dst + head * HID + lane * 2);
    float ds = hv.x * as.x + hv.y * as.y;
    float dd = hv.x * ad.x + hv.y * ad.y;
#pragma unroll
    for (int off = 16; off > 0; off >>= 1) {
        ds += __shfl_xor_sync(0xffffffffu, ds, off);
        dd += __shfl_xor_sync(0xffffffffu, dd, off);
    }
    if (lane == 0) {
        g_as[n * HEADS + head] = ds;
        g_ad[n * HEADS + head] = dd;
    }
}

// ---------------- aggregation: warp per node, ALL 4 heads (no-max softmax) ----------------
// gathers fp16 h rows (one uint4 = 8 halves per lane per edge).
// writeSplit=1: write bf16 [hi|lo|hi] splits into g_a3 (K=256 layout) for layer-2 GEMM.
// writeSplit=0: write fp32 bufB for pooling.
__global__ void k_agg(const float* __restrict__ bias, int writeSplit) {
    int wid = (blockIdx.x * blockDim.x + threadIdx.x) >> 5;
    int lane = threadIdx.x & 31;
    if (wid >= NN) return;
    int n = wid;
    int head = lane >> 3;
    int beg = g_rowptr[n], end = g_rowptr[n + 1];
    float adv = g_ad[n * HEADS + head];

    float s = 0.f;
    float a[8] = {};
    for (int p = beg; p < end; p++) {
        int sn = g_csr[p];
        float e = g_as[sn * HEADS + head] + adv;
        e = (e > 0.f) ? e : NEG_SLOPE * e;
        float w = __expf(e);
        uint4 v = *(const uint4*)(g_h16 + (size_t)sn * D1 + lane * 8);
        const __half2* hp = (const __half2*)&v;
        s += w;
#pragma unroll
        for (int q = 0; q < 4; q++) {
            float2 f = __half22float2(hp[q]);
            a[2 * q]     = fmaf(w, f.x, a[2 * q]);
            a[2 * q + 1] = fmaf(w, f.y, a[2 * q + 1]);
        }
    }
    float inv = 1.f / s;
    const float* bp = bias + lane * 8;
    float o[8];
#pragma unroll
    for (int q = 0; q < 8; q++) {
        float v = a[q] * inv + bp[q];
        o[q] = (v > 0.f) ? v : expm1f(v);
    }
    if (!writeSplit) {
        float4* w0 = (float4*)g_bufB + (size_t)n * (D1 / 4) + lane * 2;
        w0[0] = make_float4(o[0], o[1], o[2], o[3]);
        w0[1] = make_float4(o[4], o[5], o[6], o[7]);
    } else {
        __nv_bfloat16 hi8[8], lo8[8];
#pragma unroll
        for (int q = 0; q < 8; q++) {
            __nv_bfloat16 hi = __float2bfloat16(o[q]);
            hi8[q] = hi;
            lo8[q] = __float2bfloat16(o[q] - __bfloat162float(hi));
        }
        __nv_bfloat16* dst = g_a3 + (size_t)n * (3 * D1) + lane * 8;
        *(uint4*)(dst)          = *(uint4*)hi8;
        *(uint4*)(dst + D1)     = *(uint4*)lo8;
        *(uint4*)(dst + 2 * D1) = *(uint4*)hi8;
    }
}

// ---------------- global mean pool (batch sorted int32), reads g_bufB ----------------
__device__ int lower_bound_i(const int* a, int n, int v) {
    int lo = 0, hi = n;
    while (lo < hi) {
        int mid = (lo + hi) >> 1;
        if (a[mid] < v) lo = mid + 1; else hi = mid;
    }
    return lo;
}

__global__ void k_pool(const int* __restrict__ batch) {
    __shared__ int s_lo, s_hi;
    int g = blockIdx.x;
    int tid = threadIdx.x;
    if (tid == 0) {
        s_lo = lower_bound_i(batch, NN, g);
        s_hi = lower_bound_i(batch, NN, g + 1);
    }
    __syncthreads();
    int lo = s_lo, hi = s_hi;
    float acc = 0.f;
    for (int n = lo; n < hi; n++) acc += g_bufB[(size_t)n * D1 + tid];
    float cnt = (float)(hi - lo);
    g_pooled[g * D1 + tid] = acc / fmaxf(cnt, 1.f);
}

// ---------------- final linear ----------------
__global__ void k_fc(const float* __restrict__ fc_w, const float* __restrict__ fc_b,
                     float* __restrict__ out) {
    __shared__ float sp[D1];
    int g = blockIdx.x;
    int tid = threadIdx.x;  // 64 threads
    for (int i = tid; i < D1; i += 64) sp[i] = g_pooled[g * D1 + i];
    __syncthreads();
    float acc = fc_b[tid];
#pragma unroll 8
    for (int k = 0; k < D1; k++) acc += sp[k] * fc_w[k * OUT_F + tid];
    out[g * OUT_F + tid] = acc;
}

// ---------------- launch (pure kernel launches; no runtime APIs) ----------------
extern "C" void kernel_launch(void* const* d_in, const int* in_sizes, int n_in,
                              void* d_out, int out_size) {
    const float* x        = (const float*)d_in[0];
    const int*   ei       = (const int*)d_in[1];
    const int*   bat      = (const int*)d_in[2];
    const float* W1       = (const float*)d_in[3];
    const float* att_src1 = (const float*)d_in[4];
    const float* att_dst1 = (const float*)d_in[5];
    const float* b1       = (const float*)d_in[6];
    const float* W2       = (const float*)d_in[7];
    const float* att_src2 = (const float*)d_in[8];
    const float* att_dst2 = (const float*)d_in[9];
    const float* b2       = (const float*)d_in[10];
    const float* fc_w     = (const float*)d_in[11];
    const float* fc_b     = (const float*)d_in[12];
    float* out = (float*)d_out;

    const int ZB = 256;
    // CSR build
    k_zero<<<196, ZB>>>();
    k_hist<<<(ET + ZB - 1) / ZB, ZB>>>(ei);
    int nb = (NN + 4095) / 4096;  // 13
    k_scan_part<<<nb, 1024>>>();
    k_scan_sums<<<1, 32>>>(nb);
    k_scan_add<<<(NN + ZB - 1) / ZB, ZB>>>();
    k_fill_csr<<<(ET + ZB - 1) / ZB, ZB>>>(ei);

    dim3 tcgrid(2, MPAD / 128);
    int logitBlocks = (NN * HEADS * 32 + 255) / 256;
    int aggBlocks   = (NN * 32 + 255) / 256;

    // layer 1: K = 128 (kbits 7), K3 = 384; agg writes layer-2 splits directly
    k_split_w<<<(D1 << 7) / ZB, ZB>>>(W1, 7);
    k_split_a<<<(int)(((long long)MPAD << 7) / ZB), ZB>>>(x, 7);
    k_gemm_mma<<<tcgrid, 256>>>(384);
    k_logits<<<logitBlocks, 256>>>(att_src1, att_dst1);
    k_agg<<<aggBlocks, 256>>>(b1, 1);

    // layer 2: K = 256, K3 = 768 (A' already written by layer-1 agg)
    k_split_w<<<(D1 << 8) / ZB, ZB>>>(W2, 8);
    k_gemm_mma<<<tcgrid, 256>>>(768);
    k_logits<<<logitBlocks, 256>>>(att_src2, att_dst2);
    k_agg<<<aggBlocks, 256>>>(b2, 0);

    // pool + fc
    k_pool<<<NGRAPH, D1>>>(bat);
    k_fc<<<NGRAPH, OUT_F>>>(fc_w, fc_b, out);
}